// round 15
// baseline (speedup 1.0000x reference)
#include <cuda_runtime.h>
#include <cstdint>

// Problem constants (fixed shapes for this problem instance)
#define B_ 32
#define T_ 10
#define P_ 25
#define H_ 100
#define W_ 100

#define NPTS      (B_ * T_ * P_)             // 8000 points
#define OUT_ELEMS (B_ * T_ * H_ * W_ * P_)   // 80,000,000 floats = 320 MB
#define OUT_VEC8  (OUT_ELEMS / 8)            // 10,000,000 32B granules

#define FILL_BLOCKS  1184                    // 148 SMs * 8
#define FILL_THREADS 1024

#define L1_WORDS (OUT_VEC8 / 32)             // 312,500  (1 bit / granule)
#define L2_WORDS (OUT_VEC8 / 4)              // 2,500,000 (1 byte / granule = per-elem bits)

// Bitmaps. Static zero-init; every kernel execution leaves them zeroed again
// (fill clears what set_bits set) -> deterministic across graph replays.
__device__ uint32_t g_l1[L1_WORDS];
__device__ uint32_t g_l2[L2_WORDS];

// 256-bit streaming stores (sm_100+)
__device__ __forceinline__ void st_zero_256(float* p) {
    asm volatile(
        "st.global.cs.v8.f32 [%0], {%1, %1, %1, %1, %1, %1, %1, %1};"
        :: "l"(p), "f"(0.0f) : "memory");
}
__device__ __forceinline__ void st_val_256(float* p, const float* v) {
    asm volatile(
        "st.global.cs.v8.f32 [%0], {%1, %2, %3, %4, %5, %6, %7, %8};"
        :: "l"(p), "f"(v[0]), "f"(v[1]), "f"(v[2]), "f"(v[3]),
                   "f"(v[4]), "f"(v[5]), "f"(v[6]), "f"(v[7]) : "memory");
}

// ---------------------------------------------------------------------------
// Prepass: mark target elements. One thread per (b, t, p).
// Truncating (int) cast == astype(int32). No collisions in the OUTPUT (each
// point owns a distinct innermost-p slot); bitmap word collisions are handled
// by atomicOr.
// ---------------------------------------------------------------------------
__global__ void __launch_bounds__(128) set_bits_kernel(
        const float* __restrict__ x,
        const float* __restrict__ resolution,
        const float* __restrict__ origin) {
    int i = blockIdx.x * blockDim.x + threadIdx.x;
    if (i >= NPTS) return;

    int p  = i % P_;
    int bt = i / P_;          // b*T + t

    const float2 pxy = *(const float2*)(x + (size_t)bt * (2 * P_) + 2 * p);
    const float2 res = *(const float2*)(resolution + 2 * bt);
    const float2 org = *(const float2*)(origin + 2 * bt);

    int row = (int)(pxy.y / res.x + org.x);
    int col = (int)(pxy.x / res.y + org.y);

    if (row >= 0 && row < H_ && col >= 0 && col < W_) {
        uint32_t idx = ((((uint32_t)bt * H_ + row) * W_) + col) * P_ + p;  // < 80M
        uint32_t g = idx >> 3;          // granule
        uint32_t e = idx & 7;           // element within granule
        atomicOr(&g_l1[g >> 5], 1u << (g & 31));
        atomicOr(&g_l2[g >> 2], (1u << e) << ((g & 3) * 8));
    }
}

// ---------------------------------------------------------------------------
// Fill-with-override: grid-stride over 32B granules, 8-way unrolled streaming
// stores. Per granule: one warp-broadcast L1-bitmap load (32 lanes -> 1 word)
// and a warp-uniform w==0 branch; ~99.92% of granules take the pure-zero
// path. Marked granules merge the 1.0f pattern from the per-element byte.
// The kernel re-zeroes every nonzero bitmap word/byte it consumes.
// PDL secondary: gridsync at top waits for set_bits (launch latency hidden).
// ---------------------------------------------------------------------------
__device__ __forceinline__ void do_granule(float* __restrict__ outf,
                                           size_t g, uint32_t w, unsigned lane) {
    if (w == 0) {                       // warp-uniform
        st_zero_256(outf + 8 * g);
    } else {
        uint8_t b = 0;
        if ((w >> lane) & 1u) {
            b = ((const uint8_t*)g_l2)[g];
        }
        float v[8];
#pragma unroll
        for (int e = 0; e < 8; e++) {
            v[e] = ((b >> e) & 1) ? 1.0f : 0.0f;
        }
        st_val_256(outf + 8 * g, v);
        if (b) {                        // clear per-element byte (distinct bytes, no race)
            ((uint8_t*)g_l2)[g] = 0;
        }
        if (lane == 0) {                // word is exclusive to this warp-batch
            g_l1[g >> 5] = 0;
        }
    }
}

__global__ void __launch_bounds__(FILL_THREADS) fill_apply_kernel(float* __restrict__ outf) {
    cudaGridDependencySynchronize();    // wait for set_bits' bitmap writes

    const size_t stride = (size_t)FILL_BLOCKS * FILL_THREADS;  // 1,212,416 (div by 32)
    size_t i = (size_t)blockIdx.x * FILL_THREADS + threadIdx.x;
    const unsigned lane = threadIdx.x & 31;

    const size_t end8 = (size_t)OUT_VEC8 > 7 * stride ? (size_t)OUT_VEC8 - 7 * stride : 0;
    for (; i < end8; i += 8 * stride) {
        // Batch the 8 broadcast bitmap loads first (independent), then store.
        uint32_t w0 = g_l1[(i             ) >> 5];
        uint32_t w1 = g_l1[(i +     stride) >> 5];
        uint32_t w2 = g_l1[(i + 2 * stride) >> 5];
        uint32_t w3 = g_l1[(i + 3 * stride) >> 5];
        uint32_t w4 = g_l1[(i + 4 * stride) >> 5];
        uint32_t w5 = g_l1[(i + 5 * stride) >> 5];
        uint32_t w6 = g_l1[(i + 6 * stride) >> 5];
        uint32_t w7 = g_l1[(i + 7 * stride) >> 5];
        do_granule(outf, i,              w0, lane);
        do_granule(outf, i +     stride, w1, lane);
        do_granule(outf, i + 2 * stride, w2, lane);
        do_granule(outf, i + 3 * stride, w3, lane);
        do_granule(outf, i + 4 * stride, w4, lane);
        do_granule(outf, i + 5 * stride, w5, lane);
        do_granule(outf, i + 6 * stride, w6, lane);
        do_granule(outf, i + 7 * stride, w7, lane);
    }
    for (; i < (size_t)OUT_VEC8; i += stride) {
        uint32_t w = g_l1[i >> 5];
        do_granule(outf, i, w, lane);
    }
}

extern "C" void kernel_launch(void* const* d_in, const int* in_sizes, int n_in,
                              void* d_out, int out_size) {
    const float* x          = (const float*)d_in[0];
    const float* resolution = (const float*)d_in[1];
    const float* origin     = (const float*)d_in[2];
    float* out = (float*)d_out;

    // 1) mark the <=8000 target elements in the bitmaps
    {
        const int threads = 128;
        const int blocks  = (NPTS + threads - 1) / threads;  // 63
        set_bits_kernel<<<blocks, threads>>>(x, resolution, origin);
    }

    // 2) fill 320MB with zeros + merged 1.0f overrides (PDL: launch latency
    //    hidden under the prepass; gridsync in-kernel orders bitmap reads)
    {
        cudaLaunchConfig_t cfg = {};
        cfg.gridDim  = dim3(FILL_BLOCKS);
        cfg.blockDim = dim3(FILL_THREADS);
        cfg.dynamicSmemBytes = 0;
        cfg.stream = 0;

        cudaLaunchAttribute attrs[1];
        attrs[0].id = cudaLaunchAttributeProgrammaticStreamSerialization;
        attrs[0].val.programmaticStreamSerializationAllowed = 1;
        cfg.attrs = attrs;
        cfg.numAttrs = 1;

        cudaLaunchKernelEx(&cfg, fill_apply_kernel, out);
    }
}